// round 14
// baseline (speedup 1.0000x reference)
#include <cuda_runtime.h>
#include <cstdint>

#define N_NODES   100000
#define N_EDGES   1600000
#define D         32
#define OUT_FEAT  32

__device__ __align__(16) float g_agg[N_NODES * D];       // segment_sum result
__device__ __align__(16) float g_partial[N_NODES * D];   // node@W1[0:32] + gb

#define TPB  128
#define NB   128
#define XSTR 33

#define P_BLOCKS     782                      // ceil(100000 / 128)
#define EPB          256                      // edges per scatter block (2/thread)
#define S_BLOCKS     (N_EDGES / EPB)          // 6250 exactly
#define T_BLOCKS     (S_BLOCKS + P_BLOCKS)    // 7032

// dyn smem: scatter path stages EPB*32 floats (32KB);
// partial path needs xs[128][33]+w1a+gb (17.1KB). Take max = 8192 floats.
#define SMEM1_FLOATS 8192
#define SMEM2_FLOATS (NB * XSTR + 32 * 32 + 32 * 32 + 32)

#define PDL_TRIGGER() asm volatile("griddepcontrol.launch_dependents;" ::: "memory")
#define PDL_WAIT()    asm volatile("griddepcontrol.wait;" ::: "memory")

// ---------------------------------------------------------------------------
// Kernel 0: zero g_agg (PDL primary; fused prefetch overlaps the zeroing).
// ---------------------------------------------------------------------------
#define Z_BLOCKS 1600
__global__ __launch_bounds__(TPB) void zero_kernel() {
    PDL_TRIGGER();
    float4* p = reinterpret_cast<float4*>(g_agg);
    const int i0 = blockIdx.x * (TPB * 4) + threadIdx.x;
    const float4 z = make_float4(0.f, 0.f, 0.f, 0.f);
    #pragma unroll
    for (int t = 0; t < 4; t++) p[i0 + TPB * t] = z;
}

// ---------------------------------------------------------------------------
// Kernel 1 (fused): scatter blocks stage 256 edges in smem and issue TWO
// cp.reduce.async.bulk (128B) per thread — TMA/L2-side RMW, half the
// per-block overhead of the 128-edge version. Partial-MLP Bresenham-mixed.
// ---------------------------------------------------------------------------
__global__ __launch_bounds__(TPB) void fused_scatter_partial(
    const float* __restrict__ edge_attr,
    const int* __restrict__ receivers,
    const float* __restrict__ node_attr,
    const float* __restrict__ global_attr,
    const float* __restrict__ W1,
    const float* __restrict__ b1)
{
    PDL_TRIGGER();
    const int tid = threadIdx.x;

    const long long a = (long long)blockIdx.x * P_BLOCKS;
    const int p_before = (int)(a / T_BLOCKS);
    const int p_after  = (int)((a + P_BLOCKS) / T_BLOCKS);
    const bool is_partial = (p_after > p_before);

    extern __shared__ float smem[];

    if (!is_partial) {
        // -------- scatter via TMA bulk-reduce, 2 edges/thread ----------------
        float4* b4 = reinterpret_cast<float4*>(smem);   // 2048 f4 = 256 edges
        const int s_idx = blockIdx.x - p_before;        // 0..S_BLOCKS-1
        const int e0 = s_idx * EPB;

        // coalesced prefetch: 16 independent LDG.128 + 2 receiver loads
        const float4* src = reinterpret_cast<const float4*>(edge_attr) + (size_t)e0 * 8;
        float4 v[16];
        #pragma unroll
        for (int t = 0; t < 16; t++) v[t] = src[tid + 128 * t];
        const int r0 = receivers[e0 + tid];
        const int r1 = receivers[e0 + tid + 128];

        // stage edges contiguously: edge e at smem bytes [e*128, e*128+128)
        #pragma unroll
        for (int t = 0; t < 16; t++) b4[tid + 128 * t] = v[t];

        asm volatile("fence.proxy.async.shared::cta;" ::: "memory");
        __syncthreads();

        PDL_WAIT();   // g_agg fully zeroed beyond this point

        uint32_t sb;
        asm("{ .reg .u64 t; cvta.to.shared.u64 t, %1; cvt.u32.u64 %0, t; }"
            : "=r"(sb) : "l"(smem));

        if ((unsigned)r0 < N_NODES) {
            float* dst = g_agg + (size_t)r0 * D;
            asm volatile(
                "cp.reduce.async.bulk.global.shared::cta.bulk_group.add.f32 "
                "[%0], [%1], 128;"
                :: "l"(dst), "r"(sb + (unsigned)tid * 128)
                : "memory");
        }
        if ((unsigned)r1 < N_NODES) {
            float* dst = g_agg + (size_t)r1 * D;
            asm volatile(
                "cp.reduce.async.bulk.global.shared::cta.bulk_group.add.f32 "
                "[%0], [%1], 128;"
                :: "l"(dst), "r"(sb + (unsigned)(tid + 128) * 128)
                : "memory");
        }
        asm volatile("cp.async.bulk.commit_group;" ::: "memory");
        asm volatile("cp.async.bulk.wait_group 0;" ::: "memory");
        return;
    }

    // -------- partial-MLP path (unchanged, proven) ---------------------------
    float* xs  = smem;                 // [NB][XSTR]
    float* w1s = xs + NB * XSTR;       // [32][32]  W1 rows 0..31
    float* gb  = w1s + 32 * 32;        // [32]

    const int cg   = tid & 3;
    const int q    = tid >> 2;
    const int base = p_before * NB;
    const int nvalid = min(NB, N_NODES - base);
    const bool full  = (nvalid == NB);

    {
        const float4* w1v = reinterpret_cast<const float4*>(W1);
        float4 a0 = w1v[tid], a1 = w1v[tid + 128];
        reinterpret_cast<float4*>(w1s)[tid]       = a0;
        reinterpret_cast<float4*>(w1s)[tid + 128] = a1;
    }
    if (tid < 32) {
        float acc = b1[tid];
        #pragma unroll
        for (int k = 0; k < D; k++)
            acc = fmaf(global_attr[k], W1[(64 + k) * 32 + tid], acc);
        gb[tid] = acc;
    }
    {
        const float4* nav = reinterpret_cast<const float4*>(node_attr) + (size_t)base * 8;
        float4 va[8];
        #pragma unroll
        for (int t = 0; t < 8; t++) {
            int idx = tid + 128 * t;
            if (full || (idx >> 3) < nvalid) va[t] = nav[idx];
            else va[t] = make_float4(0, 0, 0, 0);
        }
        #pragma unroll
        for (int t = 0; t < 8; t++) {
            int idx = tid + 128 * t;
            int n = idx >> 3, c = idx & 7;
            float* p = &xs[n * XSTR + 4 * c];
            p[0] = va[t].x; p[1] = va[t].y; p[2] = va[t].z; p[3] = va[t].w;
        }
    }
    __syncthreads();

    float acc[4][8];
    #pragma unroll
    for (int j = 0; j < 4; j++)
        #pragma unroll
        for (int m = 0; m < 8; m++) acc[j][m] = gb[cg * 8 + m];

    const float* x0 = &xs[(4 * q + 0) * XSTR];
    const float* x1 = &xs[(4 * q + 1) * XSTR];
    const float* x2 = &xs[(4 * q + 2) * XSTR];
    const float* x3 = &xs[(4 * q + 3) * XSTR];

    #pragma unroll 4
    for (int k = 0; k < 32; k++) {
        float4 wa = *reinterpret_cast<const float4*>(&w1s[k * 32 + cg * 8]);
        float4 wb = *reinterpret_cast<const float4*>(&w1s[k * 32 + cg * 8 + 4]);
        float w[8] = {wa.x, wa.y, wa.z, wa.w, wb.x, wb.y, wb.z, wb.w};
        float xv[4] = {x0[k], x1[k], x2[k], x3[k]};
        #pragma unroll
        for (int j = 0; j < 4; j++)
            #pragma unroll
            for (int m = 0; m < 8; m++)
                acc[j][m] = fmaf(xv[j], w[m], acc[j][m]);
    }

    #pragma unroll
    for (int j = 0; j < 4; j++) {
        int n = 4 * q + j;
        if (n < nvalid) {
            float* dst = g_partial + (size_t)(base + n) * D + cg * 8;
            reinterpret_cast<float4*>(dst)[0] =
                make_float4(acc[j][0], acc[j][1], acc[j][2], acc[j][3]);
            reinterpret_cast<float4*>(dst)[1] =
                make_float4(acc[j][4], acc[j][5], acc[j][6], acc[j][7]);
        }
    }
}

// ---------------------------------------------------------------------------
// Kernel 2 (PDL secondary): weights staged pre-wait; then agg/P + MLP.
// ---------------------------------------------------------------------------
__global__ __launch_bounds__(TPB) void final_kernel(
    const float* __restrict__ W1,
    const float* __restrict__ W2, const float* __restrict__ b2,
    float* __restrict__ out)
{
    extern __shared__ float smem[];
    float* xs  = smem;                 // [NB][XSTR] agg; reused as ht
    float* w1s = xs + NB * XSTR;       // [32][32]  W1 rows 32..63
    float* w2s = w1s + 32 * 32;        // [32][32]
    float* b2s = w2s + 32 * 32;        // [32]

    const int tid  = threadIdx.x;
    const int cg   = tid & 3;
    const int q    = tid >> 2;
    const int base = blockIdx.x * NB;
    const int nvalid = min(NB, N_NODES - base);
    const bool full  = (nvalid == NB);

    {
        const float4* w1v = reinterpret_cast<const float4*>(W1);
        const float4* w2v = reinterpret_cast<const float4*>(W2);
        float4 a0 = w1v[256 + tid], a1 = w1v[256 + tid + 128];
        float4 c0 = w2v[tid],       c1 = w2v[tid + 128];
        reinterpret_cast<float4*>(w1s)[tid]       = a0;
        reinterpret_cast<float4*>(w1s)[tid + 128] = a1;
        reinterpret_cast<float4*>(w2s)[tid]       = c0;
        reinterpret_cast<float4*>(w2s)[tid + 128] = c1;
    }
    if (tid < 32) b2s[tid] = b2[tid];

    PDL_WAIT();   // g_agg and g_partial complete beyond this point

    {
        const float4* agv = reinterpret_cast<const float4*>(g_agg) + (size_t)base * 8;
        float4 vb[8];
        #pragma unroll
        for (int t = 0; t < 8; t++) {
            int idx = tid + 128 * t;
            if (full || (idx >> 3) < nvalid) vb[t] = agv[idx];
            else vb[t] = make_float4(0, 0, 0, 0);
        }
        #pragma unroll
        for (int t = 0; t < 8; t++) {
            int idx = tid + 128 * t;
            int n = idx >> 3, c = idx & 7;
            float* p = &xs[n * XSTR + 4 * c];
            p[0] = vb[t].x; p[1] = vb[t].y; p[2] = vb[t].z; p[3] = vb[t].w;
        }
    }

    float acc[4][8];
    {
        const float4* pv = reinterpret_cast<const float4*>(g_partial) + (size_t)base * 8;
        #pragma unroll
        for (int j = 0; j < 4; j++) {
            int n = 4 * q + j;
            float4 pa, pb;
            if (full || n < nvalid) {
                pa = pv[n * 8 + cg * 2];
                pb = pv[n * 8 + cg * 2 + 1];
            } else { pa = make_float4(0,0,0,0); pb = pa; }
            acc[j][0] = pa.x; acc[j][1] = pa.y; acc[j][2] = pa.z; acc[j][3] = pa.w;
            acc[j][4] = pb.x; acc[j][5] = pb.y; acc[j][6] = pb.z; acc[j][7] = pb.w;
        }
    }
    __syncthreads();

    const float* x0 = &xs[(4 * q + 0) * XSTR];
    const float* x1 = &xs[(4 * q + 1) * XSTR];
    const float* x2 = &xs[(4 * q + 2) * XSTR];
    const float* x3 = &xs[(4 * q + 3) * XSTR];

    #pragma unroll 4
    for (int k = 0; k < 32; k++) {
        float4 wa = *reinterpret_cast<const float4*>(&w1s[k * 32 + cg * 8]);
        float4 wb = *reinterpret_cast<const float4*>(&w1s[k * 32 + cg * 8 + 4]);
        float w[8] = {wa.x, wa.y, wa.z, wa.w, wb.x, wb.y, wb.z, wb.w};
        float xv[4] = {x0[k], x1[k], x2[k], x3[k]};
        #pragma unroll
        for (int j = 0; j < 4; j++)
            #pragma unroll
            for (int m = 0; m < 8; m++)
                acc[j][m] = fmaf(xv[j], w[m], acc[j][m]);
    }

    __syncthreads();
    float* ht = xs;
    #pragma unroll
    for (int j = 0; j < 4; j++) {
        int n = 4 * q + j;
        #pragma unroll
        for (int m = 0; m < 8; m++)
            ht[n * XSTR + cg * 8 + m] = fmaxf(acc[j][m], 0.f);
    }
    __syncthreads();

    float o[4][8];
    #pragma unroll
    for (int j = 0; j < 4; j++)
        #pragma unroll
        for (int m = 0; m < 8; m++) o[j][m] = b2s[cg * 8 + m];

    const float* h0 = &ht[(4 * q + 0) * XSTR];
    const float* h1 = &ht[(4 * q + 1) * XSTR];
    const float* h2 = &ht[(4 * q + 2) * XSTR];
    const float* h3 = &ht[(4 * q + 3) * XSTR];

    #pragma unroll 4
    for (int i = 0; i < 32; i++) {
        float4 wa = *reinterpret_cast<const float4*>(&w2s[i * 32 + cg * 8]);
        float4 wb = *reinterpret_cast<const float4*>(&w2s[i * 32 + cg * 8 + 4]);
        float w[8] = {wa.x, wa.y, wa.z, wa.w, wb.x, wb.y, wb.z, wb.w};
        float hv[4] = {h0[i], h1[i], h2[i], h3[i]};
        #pragma unroll
        for (int j = 0; j < 4; j++)
            #pragma unroll
            for (int m = 0; m < 8; m++)
                o[j][m] = fmaf(hv[j], w[m], o[j][m]);
    }

    #pragma unroll
    for (int j = 0; j < 4; j++) {
        int n = 4 * q + j;
        if (n < nvalid) {
            float* dst = out + (size_t)(base + n) * OUT_FEAT + cg * 8;
            reinterpret_cast<float4*>(dst)[0] =
                make_float4(o[j][0], o[j][1], o[j][2], o[j][3]);
            reinterpret_cast<float4*>(dst)[1] =
                make_float4(o[j][4], o[j][5], o[j][6], o[j][7]);
        }
    }
}

// ---------------------------------------------------------------------------
// Launch: zero ->(PDL) fused ->(PDL) final.
// ---------------------------------------------------------------------------
static void launch_pdl(const void* func, dim3 grid, dim3 block, size_t smem,
                       void** args) {
    cudaLaunchConfig_t cfg = {};
    cfg.gridDim = grid;
    cfg.blockDim = block;
    cfg.dynamicSmemBytes = smem;
    cudaLaunchAttribute attr[1];
    attr[0].id = cudaLaunchAttributeProgrammaticStreamSerialization;
    attr[0].val.programmaticStreamSerializationAllowed = 1;
    cfg.attrs = attr;
    cfg.numAttrs = 1;
    cudaLaunchKernelExC(&cfg, func, args);
}

extern "C" void kernel_launch(void* const* d_in, const int* in_sizes, int n_in,
                              void* d_out, int out_size) {
    const float* node_attr   = (const float*)d_in[0];
    const int*   edge_index  = (const int*)d_in[1];
    const float* edge_attr   = (const float*)d_in[2];
    const float* global_attr = (const float*)d_in[3];
    const float* W1          = (const float*)d_in[4];
    const float* b1          = (const float*)d_in[5];
    const float* W2          = (const float*)d_in[6];
    const float* b2          = (const float*)d_in[7];
    float*       out         = (float*)d_out;

    const int* receivers = edge_index + N_EDGES;

    zero_kernel<<<Z_BLOCKS, TPB>>>();

    {
        void* args[] = { (void*)&edge_attr, (void*)&receivers,
                         (void*)&node_attr, (void*)&global_attr,
                         (void*)&W1, (void*)&b1 };
        launch_pdl((const void*)fused_scatter_partial,
                   dim3(T_BLOCKS), dim3(TPB),
                   SMEM1_FLOATS * sizeof(float), args);
    }

    {
        void* args[] = { (void*)&W1, (void*)&W2, (void*)&b2, (void*)&out };
        launch_pdl((const void*)final_kernel,
                   dim3(P_BLOCKS), dim3(TPB),
                   SMEM2_FLOATS * sizeof(float), args);
    }
    (void)in_sizes; (void)n_in; (void)out_size;
}

// round 15
// speedup vs baseline: 1.0791x; 1.0791x over previous
#include <cuda_runtime.h>
#include <cstdint>

#define N_NODES   100000
#define N_EDGES   1600000
#define D         32
#define OUT_FEAT  32

__device__ __align__(16) float g_agg[N_NODES * D];       // segment_sum result
__device__ __align__(16) float g_partial[N_NODES * D];   // node@W1[0:32] + gb

#define TPB  128
#define NB   128
#define XSTR 33

#define P_BLOCKS     782                      // ceil(100000 / 128)
#define EPB          128                      // edges per scatter block
#define S_BLOCKS     (N_EDGES / EPB)          // 12500 exactly
#define T_BLOCKS     (S_BLOCKS + P_BLOCKS)    // 13282

// dyn smem: scatter path uses EPB*32 floats (16KB) staged edges;
// partial path uses xs[128][33] + w1a[32][32] + gb[32] (17.1KB). Take max.
#define SMEM1_FLOATS (NB * XSTR + 32 * 32 + 32)
#define SMEM2_FLOATS (NB * XSTR + 32 * 32 + 32 * 32 + 32)

#define PDL_TRIGGER() asm volatile("griddepcontrol.launch_dependents;" ::: "memory")
#define PDL_WAIT()    asm volatile("griddepcontrol.wait;" ::: "memory")

// ---------------------------------------------------------------------------
// Kernel 0: zero g_agg (PDL primary; fused prefetch overlaps the zeroing).
// ---------------------------------------------------------------------------
#define Z_BLOCKS 1600
__global__ __launch_bounds__(TPB) void zero_kernel() {
    PDL_TRIGGER();
    float4* p = reinterpret_cast<float4*>(g_agg);
    const int i0 = blockIdx.x * (TPB * 4) + threadIdx.x;
    const float4 z = make_float4(0.f, 0.f, 0.f, 0.f);
    #pragma unroll
    for (int t = 0; t < 4; t++) p[i0 + TPB * t] = z;
}

// ---------------------------------------------------------------------------
// Kernel 1 (fused): scatter blocks stage 128 edges in smem and issue ONE
// cp.reduce.async.bulk (128B) per edge — 8x fewer SM-issue ops than red.v4,
// RMW done by the TMA/L2 path. Partial-MLP blocks Bresenham-interleaved.
// ---------------------------------------------------------------------------
__global__ __launch_bounds__(TPB) void fused_scatter_partial(
    const float* __restrict__ edge_attr,
    const int* __restrict__ receivers,
    const float* __restrict__ node_attr,
    const float* __restrict__ global_attr,
    const float* __restrict__ W1,
    const float* __restrict__ b1)
{
    PDL_TRIGGER();
    const int tid = threadIdx.x;

    const long long a = (long long)blockIdx.x * P_BLOCKS;
    const int p_before = (int)(a / T_BLOCKS);
    const int p_after  = (int)((a + P_BLOCKS) / T_BLOCKS);
    const bool is_partial = (p_after > p_before);

    extern __shared__ float smem[];

    if (!is_partial) {
        // -------- scatter via TMA bulk-reduce --------------------------------
        float4* b4 = reinterpret_cast<float4*>(smem);   // 1024 f4 = 128 edges
        const int s_idx = blockIdx.x - p_before;        // 0..S_BLOCKS-1
        const int e0 = s_idx * EPB;

        // coalesced prefetch: 8 independent LDG.128 per thread (inputs only)
        const float4* src = reinterpret_cast<const float4*>(edge_attr) + (size_t)e0 * 8;
        float4 v[8];
        #pragma unroll
        for (int t = 0; t < 8; t++) v[t] = src[tid + 128 * t];
        const int r = receivers[e0 + tid];              // this thread's edge

        // stage edges contiguously: edge e occupies smem bytes [e*128, e*128+128)
        #pragma unroll
        for (int t = 0; t < 8; t++) b4[tid + 128 * t] = v[t];

        // make generic-proxy STS visible to the async (TMA) proxy
        asm volatile("fence.proxy.async.shared::cta;" ::: "memory");
        __syncthreads();

        PDL_WAIT();   // g_agg fully zeroed beyond this point

        uint32_t sb;
        asm("{ .reg .u64 t; cvta.to.shared.u64 t, %1; cvt.u32.u64 %0, t; }"
            : "=r"(sb) : "l"(smem));

        if ((unsigned)r < N_NODES) {
            float* dst = g_agg + (size_t)r * D;         // 128B-aligned
            asm volatile(
                "cp.reduce.async.bulk.global.shared::cta.bulk_group.add.f32 "
                "[%0], [%1], 128;"
                :: "l"(dst), "r"(sb + (unsigned)tid * 128)
                : "memory");
        }
        asm volatile("cp.async.bulk.commit_group;" ::: "memory");
        // full completion: reduce writes visible before grid completes (PDL)
        asm volatile("cp.async.bulk.wait_group 0;" ::: "memory");
        return;
    }

    // -------- partial-MLP path (unchanged, proven) ---------------------------
    float* xs  = smem;                 // [NB][XSTR]
    float* w1s = xs + NB * XSTR;       // [32][32]  W1 rows 0..31
    float* gb  = w1s + 32 * 32;        // [32]

    const int cg   = tid & 3;
    const int q    = tid >> 2;
    const int base = p_before * NB;
    const int nvalid = min(NB, N_NODES - base);
    const bool full  = (nvalid == NB);

    {
        const float4* w1v = reinterpret_cast<const float4*>(W1);
        float4 a0 = w1v[tid], a1 = w1v[tid + 128];
        reinterpret_cast<float4*>(w1s)[tid]       = a0;
        reinterpret_cast<float4*>(w1s)[tid + 128] = a1;
    }
    if (tid < 32) {
        float acc = b1[tid];
        #pragma unroll
        for (int k = 0; k < D; k++)
            acc = fmaf(global_attr[k], W1[(64 + k) * 32 + tid], acc);
        gb[tid] = acc;
    }
    {
        const float4* nav = reinterpret_cast<const float4*>(node_attr) + (size_t)base * 8;
        float4 va[8];
        #pragma unroll
        for (int t = 0; t < 8; t++) {
            int idx = tid + 128 * t;
            if (full || (idx >> 3) < nvalid) va[t] = nav[idx];
            else va[t] = make_float4(0, 0, 0, 0);
        }
        #pragma unroll
        for (int t = 0; t < 8; t++) {
            int idx = tid + 128 * t;
            int n = idx >> 3, c = idx & 7;
            float* p = &xs[n * XSTR + 4 * c];
            p[0] = va[t].x; p[1] = va[t].y; p[2] = va[t].z; p[3] = va[t].w;
        }
    }
    __syncthreads();

    float acc[4][8];
    #pragma unroll
    for (int j = 0; j < 4; j++)
        #pragma unroll
        for (int m = 0; m < 8; m++) acc[j][m] = gb[cg * 8 + m];

    const float* x0 = &xs[(4 * q + 0) * XSTR];
    const float* x1 = &xs[(4 * q + 1) * XSTR];
    const float* x2 = &xs[(4 * q + 2) * XSTR];
    const float* x3 = &xs[(4 * q + 3) * XSTR];

    #pragma unroll 4
    for (int k = 0; k < 32; k++) {
        float4 wa = *reinterpret_cast<const float4*>(&w1s[k * 32 + cg * 8]);
        float4 wb = *reinterpret_cast<const float4*>(&w1s[k * 32 + cg * 8 + 4]);
        float w[8] = {wa.x, wa.y, wa.z, wa.w, wb.x, wb.y, wb.z, wb.w};
        float xv[4] = {x0[k], x1[k], x2[k], x3[k]};
        #pragma unroll
        for (int j = 0; j < 4; j++)
            #pragma unroll
            for (int m = 0; m < 8; m++)
                acc[j][m] = fmaf(xv[j], w[m], acc[j][m]);
    }

    #pragma unroll
    for (int j = 0; j < 4; j++) {
        int n = 4 * q + j;
        if (n < nvalid) {
            float* dst = g_partial + (size_t)(base + n) * D + cg * 8;
            reinterpret_cast<float4*>(dst)[0] =
                make_float4(acc[j][0], acc[j][1], acc[j][2], acc[j][3]);
            reinterpret_cast<float4*>(dst)[1] =
                make_float4(acc[j][4], acc[j][5], acc[j][6], acc[j][7]);
        }
    }
}

// ---------------------------------------------------------------------------
// Kernel 2 (PDL secondary): weights staged pre-wait; then agg/P + MLP.
// ---------------------------------------------------------------------------
__global__ __launch_bounds__(TPB) void final_kernel(
    const float* __restrict__ W1,
    const float* __restrict__ W2, const float* __restrict__ b2,
    float* __restrict__ out)
{
    extern __shared__ float smem[];
    float* xs  = smem;                 // [NB][XSTR] agg; reused as ht
    float* w1s = xs + NB * XSTR;       // [32][32]  W1 rows 32..63
    float* w2s = w1s + 32 * 32;        // [32][32]
    float* b2s = w2s + 32 * 32;        // [32]

    const int tid  = threadIdx.x;
    const int cg   = tid & 3;
    const int q    = tid >> 2;
    const int base = blockIdx.x * NB;
    const int nvalid = min(NB, N_NODES - base);
    const bool full  = (nvalid == NB);

    {
        const float4* w1v = reinterpret_cast<const float4*>(W1);
        const float4* w2v = reinterpret_cast<const float4*>(W2);
        float4 a0 = w1v[256 + tid], a1 = w1v[256 + tid + 128];
        float4 c0 = w2v[tid],       c1 = w2v[tid + 128];
        reinterpret_cast<float4*>(w1s)[tid]       = a0;
        reinterpret_cast<float4*>(w1s)[tid + 128] = a1;
        reinterpret_cast<float4*>(w2s)[tid]       = c0;
        reinterpret_cast<float4*>(w2s)[tid + 128] = c1;
    }
    if (tid < 32) b2s[tid] = b2[tid];

    PDL_WAIT();   // g_agg and g_partial complete beyond this point

    {
        const float4* agv = reinterpret_cast<const float4*>(g_agg) + (size_t)base * 8;
        float4 vb[8];
        #pragma unroll
        for (int t = 0; t < 8; t++) {
            int idx = tid + 128 * t;
            if (full || (idx >> 3) < nvalid) vb[t] = agv[idx];
            else vb[t] = make_float4(0, 0, 0, 0);
        }
        #pragma unroll
        for (int t = 0; t < 8; t++) {
            int idx = tid + 128 * t;
            int n = idx >> 3, c = idx & 7;
            float* p = &xs[n * XSTR + 4 * c];
            p[0] = vb[t].x; p[1] = vb[t].y; p[2] = vb[t].z; p[3] = vb[t].w;
        }
    }

    float acc[4][8];
    {
        const float4* pv = reinterpret_cast<const float4*>(g_partial) + (size_t)base * 8;
        #pragma unroll
        for (int j = 0; j < 4; j++) {
            int n = 4 * q + j;
            float4 pa, pb;
            if (full || n < nvalid) {
                pa = pv[n * 8 + cg * 2];
                pb = pv[n * 8 + cg * 2 + 1];
            } else { pa = make_float4(0,0,0,0); pb = pa; }
            acc[j][0] = pa.x; acc[j][1] = pa.y; acc[j][2] = pa.z; acc[j][3] = pa.w;
            acc[j][4] = pb.x; acc[j][5] = pb.y; acc[j][6] = pb.z; acc[j][7] = pb.w;
        }
    }
    __syncthreads();

    const float* x0 = &xs[(4 * q + 0) * XSTR];
    const float* x1 = &xs[(4 * q + 1) * XSTR];
    const float* x2 = &xs[(4 * q + 2) * XSTR];
    const float* x3 = &xs[(4 * q + 3) * XSTR];

    #pragma unroll 4
    for (int k = 0; k < 32; k++) {
        float4 wa = *reinterpret_cast<const float4*>(&w1s[k * 32 + cg * 8]);
        float4 wb = *reinterpret_cast<const float4*>(&w1s[k * 32 + cg * 8 + 4]);
        float w[8] = {wa.x, wa.y, wa.z, wa.w, wb.x, wb.y, wb.z, wb.w};
        float xv[4] = {x0[k], x1[k], x2[k], x3[k]};
        #pragma unroll
        for (int j = 0; j < 4; j++)
            #pragma unroll
            for (int m = 0; m < 8; m++)
                acc[j][m] = fmaf(xv[j], w[m], acc[j][m]);
    }

    __syncthreads();
    float* ht = xs;
    #pragma unroll
    for (int j = 0; j < 4; j++) {
        int n = 4 * q + j;
        #pragma unroll
        for (int m = 0; m < 8; m++)
            ht[n * XSTR + cg * 8 + m] = fmaxf(acc[j][m], 0.f);
    }
    __syncthreads();

    float o[4][8];
    #pragma unroll
    for (int j = 0; j < 4; j++)
        #pragma unroll
        for (int m = 0; m < 8; m++) o[j][m] = b2s[cg * 8 + m];

    const float* h0 = &ht[(4 * q + 0) * XSTR];
    const float* h1 = &ht[(4 * q + 1) * XSTR];
    const float* h2 = &ht[(4 * q + 2) * XSTR];
    const float* h3 = &ht[(4 * q + 3) * XSTR];

    #pragma unroll 4
    for (int i = 0; i < 32; i++) {
        float4 wa = *reinterpret_cast<const float4*>(&w2s[i * 32 + cg * 8]);
        float4 wb = *reinterpret_cast<const float4*>(&w2s[i * 32 + cg * 8 + 4]);
        float w[8] = {wa.x, wa.y, wa.z, wa.w, wb.x, wb.y, wb.z, wb.w};
        float hv[4] = {h0[i], h1[i], h2[i], h3[i]};
        #pragma unroll
        for (int j = 0; j < 4; j++)
            #pragma unroll
            for (int m = 0; m < 8; m++)
                o[j][m] = fmaf(hv[j], w[m], o[j][m]);
    }

    #pragma unroll
    for (int j = 0; j < 4; j++) {
        int n = 4 * q + j;
        if (n < nvalid) {
            float* dst = out + (size_t)(base + n) * OUT_FEAT + cg * 8;
            reinterpret_cast<float4*>(dst)[0] =
                make_float4(o[j][0], o[j][1], o[j][2], o[j][3]);
            reinterpret_cast<float4*>(dst)[1] =
                make_float4(o[j][4], o[j][5], o[j][6], o[j][7]);
        }
    }
}

// ---------------------------------------------------------------------------
// Launch: zero ->(PDL) fused ->(PDL) final.
// ---------------------------------------------------------------------------
static void launch_pdl(const void* func, dim3 grid, dim3 block, size_t smem,
                       void** args) {
    cudaLaunchConfig_t cfg = {};
    cfg.gridDim = grid;
    cfg.blockDim = block;
    cfg.dynamicSmemBytes = smem;
    cudaLaunchAttribute attr[1];
    attr[0].id = cudaLaunchAttributeProgrammaticStreamSerialization;
    attr[0].val.programmaticStreamSerializationAllowed = 1;
    cfg.attrs = attr;
    cfg.numAttrs = 1;
    cudaLaunchKernelExC(&cfg, func, args);
}

extern "C" void kernel_launch(void* const* d_in, const int* in_sizes, int n_in,
                              void* d_out, int out_size) {
    const float* node_attr   = (const float*)d_in[0];
    const int*   edge_index  = (const int*)d_in[1];
    const float* edge_attr   = (const float*)d_in[2];
    const float* global_attr = (const float*)d_in[3];
    const float* W1          = (const float*)d_in[4];
    const float* b1          = (const float*)d_in[5];
    const float* W2          = (const float*)d_in[6];
    const float* b2          = (const float*)d_in[7];
    float*       out         = (float*)d_out;

    const int* receivers = edge_index + N_EDGES;

    zero_kernel<<<Z_BLOCKS, TPB>>>();

    {
        void* args[] = { (void*)&edge_attr, (void*)&receivers,
                         (void*)&node_attr, (void*)&global_attr,
                         (void*)&W1, (void*)&b1 };
        launch_pdl((const void*)fused_scatter_partial,
                   dim3(T_BLOCKS), dim3(TPB),
                   SMEM1_FLOATS * sizeof(float), args);
    }

    {
        void* args[] = { (void*)&W1, (void*)&W2, (void*)&b2, (void*)&out };
        launch_pdl((const void*)final_kernel,
                   dim3(P_BLOCKS), dim3(TPB),
                   SMEM2_FLOATS * sizeof(float), args);
    }
    (void)in_sizes; (void)n_in; (void)out_size;
}

// round 16
// speedup vs baseline: 1.0824x; 1.0031x over previous
#include <cuda_runtime.h>
#include <cstdint>

#define N_NODES   100000
#define N_EDGES   1600000
#define D         32
#define OUT_FEAT  32

__device__ __align__(16) float g_agg[N_NODES * D];       // segment_sum result
__device__ __align__(16) float g_partial[N_NODES * D];   // node@W1[0:32] + gb

#define TPB  128
#define NB   128
#define XSTR 33

#define P_BLOCKS     782                      // ceil(100000 / 128)
#define EPB          128                      // edges per scatter block
#define S_BLOCKS     (N_EDGES / EPB)          // 12500 exactly
#define T_BLOCKS     (S_BLOCKS + P_BLOCKS)    // 13282

#define SMEM1_FLOATS (NB * XSTR + 32 * 32 + 32)

// final kernel: TPB=64, NB=64 (same 4x8 per-thread tile, 2x the blocks)
#define FTPB 64
#define FNB  64
#define F_BLOCKS ((N_NODES + FNB - 1) / FNB)  // 1563
#define SMEM2_FLOATS (FNB * XSTR + 32 * 32 + 32 * 32 + 32)

#define PDL_TRIGGER() asm volatile("griddepcontrol.launch_dependents;" ::: "memory")
#define PDL_WAIT()    asm volatile("griddepcontrol.wait;" ::: "memory")

// ---------------------------------------------------------------------------
// Kernel 0: zero g_agg (PDL primary; fused prefetch overlaps the zeroing).
// ---------------------------------------------------------------------------
#define Z_BLOCKS 1600
__global__ __launch_bounds__(TPB) void zero_kernel() {
    PDL_TRIGGER();
    float4* p = reinterpret_cast<float4*>(g_agg);
    const int i0 = blockIdx.x * (TPB * 4) + threadIdx.x;
    const float4 z = make_float4(0.f, 0.f, 0.f, 0.f);
    #pragma unroll
    for (int t = 0; t < 4; t++) p[i0 + TPB * t] = z;
}

// ---------------------------------------------------------------------------
// Kernel 1 (fused): scatter blocks stage 128 edges in smem and issue ONE
// cp.reduce.async.bulk (128B) per edge — TMA/L2-side RMW. Partial-MLP
// blocks Bresenham-interleaved. (Proven 72.4us configuration, unchanged.)
// ---------------------------------------------------------------------------
__global__ __launch_bounds__(TPB) void fused_scatter_partial(
    const float* __restrict__ edge_attr,
    const int* __restrict__ receivers,
    const float* __restrict__ node_attr,
    const float* __restrict__ global_attr,
    const float* __restrict__ W1,
    const float* __restrict__ b1)
{
    PDL_TRIGGER();
    const int tid = threadIdx.x;

    const long long a = (long long)blockIdx.x * P_BLOCKS;
    const int p_before = (int)(a / T_BLOCKS);
    const int p_after  = (int)((a + P_BLOCKS) / T_BLOCKS);
    const bool is_partial = (p_after > p_before);

    extern __shared__ float smem[];

    if (!is_partial) {
        float4* b4 = reinterpret_cast<float4*>(smem);   // 1024 f4 = 128 edges
        const int s_idx = blockIdx.x - p_before;
        const int e0 = s_idx * EPB;

        const float4* src = reinterpret_cast<const float4*>(edge_attr) + (size_t)e0 * 8;
        float4 v[8];
        #pragma unroll
        for (int t = 0; t < 8; t++) v[t] = src[tid + 128 * t];
        const int r = receivers[e0 + tid];

        #pragma unroll
        for (int t = 0; t < 8; t++) b4[tid + 128 * t] = v[t];

        asm volatile("fence.proxy.async.shared::cta;" ::: "memory");
        __syncthreads();

        PDL_WAIT();   // g_agg fully zeroed beyond this point

        uint32_t sb;
        asm("{ .reg .u64 t; cvta.to.shared.u64 t, %1; cvt.u32.u64 %0, t; }"
            : "=r"(sb) : "l"(smem));

        if ((unsigned)r < N_NODES) {
            float* dst = g_agg + (size_t)r * D;
            asm volatile(
                "cp.reduce.async.bulk.global.shared::cta.bulk_group.add.f32 "
                "[%0], [%1], 128;"
                :: "l"(dst), "r"(sb + (unsigned)tid * 128)
                : "memory");
        }
        asm volatile("cp.async.bulk.commit_group;" ::: "memory");
        asm volatile("cp.async.bulk.wait_group 0;" ::: "memory");
        return;
    }

    // -------- partial-MLP path (unchanged, proven) ---------------------------
    float* xs  = smem;                 // [NB][XSTR]
    float* w1s = xs + NB * XSTR;       // [32][32]  W1 rows 0..31
    float* gb  = w1s + 32 * 32;        // [32]

    const int cg   = tid & 3;
    const int q    = tid >> 2;
    const int base = p_before * NB;
    const int nvalid = min(NB, N_NODES - base);
    const bool full  = (nvalid == NB);

    {
        const float4* w1v = reinterpret_cast<const float4*>(W1);
        float4 a0 = w1v[tid], a1 = w1v[tid + 128];
        reinterpret_cast<float4*>(w1s)[tid]       = a0;
        reinterpret_cast<float4*>(w1s)[tid + 128] = a1;
    }
    if (tid < 32) {
        float acc = b1[tid];
        #pragma unroll
        for (int k = 0; k < D; k++)
            acc = fmaf(global_attr[k], W1[(64 + k) * 32 + tid], acc);
        gb[tid] = acc;
    }
    {
        const float4* nav = reinterpret_cast<const float4*>(node_attr) + (size_t)base * 8;
        float4 va[8];
        #pragma unroll
        for (int t = 0; t < 8; t++) {
            int idx = tid + 128 * t;
            if (full || (idx >> 3) < nvalid) va[t] = nav[idx];
            else va[t] = make_float4(0, 0, 0, 0);
        }
        #pragma unroll
        for (int t = 0; t < 8; t++) {
            int idx = tid + 128 * t;
            int n = idx >> 3, c = idx & 7;
            float* p = &xs[n * XSTR + 4 * c];
            p[0] = va[t].x; p[1] = va[t].y; p[2] = va[t].z; p[3] = va[t].w;
        }
    }
    __syncthreads();

    float acc[4][8];
    #pragma unroll
    for (int j = 0; j < 4; j++)
        #pragma unroll
        for (int m = 0; m < 8; m++) acc[j][m] = gb[cg * 8 + m];

    const float* x0 = &xs[(4 * q + 0) * XSTR];
    const float* x1 = &xs[(4 * q + 1) * XSTR];
    const float* x2 = &xs[(4 * q + 2) * XSTR];
    const float* x3 = &xs[(4 * q + 3) * XSTR];

    #pragma unroll 4
    for (int k = 0; k < 32; k++) {
        float4 wa = *reinterpret_cast<const float4*>(&w1s[k * 32 + cg * 8]);
        float4 wb = *reinterpret_cast<const float4*>(&w1s[k * 32 + cg * 8 + 4]);
        float w[8] = {wa.x, wa.y, wa.z, wa.w, wb.x, wb.y, wb.z, wb.w};
        float xv[4] = {x0[k], x1[k], x2[k], x3[k]};
        #pragma unroll
        for (int j = 0; j < 4; j++)
            #pragma unroll
            for (int m = 0; m < 8; m++)
                acc[j][m] = fmaf(xv[j], w[m], acc[j][m]);
    }

    #pragma unroll
    for (int j = 0; j < 4; j++) {
        int n = 4 * q + j;
        if (n < nvalid) {
            float* dst = g_partial + (size_t)(base + n) * D + cg * 8;
            reinterpret_cast<float4*>(dst)[0] =
                make_float4(acc[j][0], acc[j][1], acc[j][2], acc[j][3]);
            reinterpret_cast<float4*>(dst)[1] =
                make_float4(acc[j][4], acc[j][5], acc[j][6], acc[j][7]);
        }
    }
}

// ---------------------------------------------------------------------------
// Kernel 2 (PDL secondary): TPB=64, NB=64 — same 4x8 per-thread tile as the
// proven version but 2x the blocks (1563): ~10.6 blocks/SM so the prologue
// LDG latency and barrier waits hide across co-resident blocks.
// ---------------------------------------------------------------------------
__global__ __launch_bounds__(FTPB) void final_kernel(
    const float* __restrict__ W1,
    const float* __restrict__ W2, const float* __restrict__ b2,
    float* __restrict__ out)
{
    extern __shared__ float smem[];
    float* xs  = smem;                 // [FNB][XSTR] agg; reused as ht
    float* w1s = xs + FNB * XSTR;      // [32][32]  W1 rows 32..63
    float* w2s = w1s + 32 * 32;        // [32][32]
    float* b2s = w2s + 32 * 32;        // [32]

    const int tid  = threadIdx.x;      // 0..63
    const int cg   = tid & 3;          // 8-col group
    const int q    = tid >> 2;         // 0..15 -> nodes 4q..4q+3
    const int base = blockIdx.x * FNB;
    const int nvalid = min(FNB, N_NODES - base);
    const bool full  = (nvalid == FNB);

    // -------- PRE-WAIT: weights/biases are pure inputs ----------------------
    {
        const float4* w1v = reinterpret_cast<const float4*>(W1);
        const float4* w2v = reinterpret_cast<const float4*>(W2);
        float4 a0 = w1v[256 + tid],       a1 = w1v[256 + tid + 64];
        float4 a2 = w1v[256 + tid + 128], a3 = w1v[256 + tid + 192];
        float4 c0 = w2v[tid],             c1 = w2v[tid + 64];
        float4 c2 = w2v[tid + 128],       c3 = w2v[tid + 192];
        reinterpret_cast<float4*>(w1s)[tid]       = a0;
        reinterpret_cast<float4*>(w1s)[tid + 64]  = a1;
        reinterpret_cast<float4*>(w1s)[tid + 128] = a2;
        reinterpret_cast<float4*>(w1s)[tid + 192] = a3;
        reinterpret_cast<float4*>(w2s)[tid]       = c0;
        reinterpret_cast<float4*>(w2s)[tid + 64]  = c1;
        reinterpret_cast<float4*>(w2s)[tid + 128] = c2;
        reinterpret_cast<float4*>(w2s)[tid + 192] = c3;
    }
    if (tid < 32) b2s[tid] = b2[tid];

    PDL_WAIT();   // g_agg and g_partial complete beyond this point

    // stage agg rows (L2-hot): 512 f4 -> 8 per thread
    {
        const float4* agv = reinterpret_cast<const float4*>(g_agg) + (size_t)base * 8;
        float4 vb[8];
        #pragma unroll
        for (int t = 0; t < 8; t++) {
            int idx = tid + 64 * t;
            if (full || (idx >> 3) < nvalid) vb[t] = agv[idx];
            else vb[t] = make_float4(0, 0, 0, 0);
        }
        #pragma unroll
        for (int t = 0; t < 8; t++) {
            int idx = tid + 64 * t;
            int n = idx >> 3, c = idx & 7;
            float* p = &xs[n * XSTR + 4 * c];
            p[0] = vb[t].x; p[1] = vb[t].y; p[2] = vb[t].z; p[3] = vb[t].w;
        }
    }

    // load this thread's P tile (4 nodes x 8 cols)
    float acc[4][8];
    {
        const float4* pv = reinterpret_cast<const float4*>(g_partial) + (size_t)base * 8;
        #pragma unroll
        for (int j = 0; j < 4; j++) {
            int n = 4 * q + j;
            float4 pa, pb;
            if (full || n < nvalid) {
                pa = pv[n * 8 + cg * 2];
                pb = pv[n * 8 + cg * 2 + 1];
            } else { pa = make_float4(0,0,0,0); pb = pa; }
            acc[j][0] = pa.x; acc[j][1] = pa.y; acc[j][2] = pa.z; acc[j][3] = pa.w;
            acc[j][4] = pb.x; acc[j][5] = pb.y; acc[j][6] = pb.z; acc[j][7] = pb.w;
        }
    }
    __syncthreads();

    // layer 1 remainder: += agg @ W1[32:64]
    const float* x0 = &xs[(4 * q + 0) * XSTR];
    const float* x1 = &xs[(4 * q + 1) * XSTR];
    const float* x2 = &xs[(4 * q + 2) * XSTR];
    const float* x3 = &xs[(4 * q + 3) * XSTR];

    #pragma unroll 4
    for (int k = 0; k < 32; k++) {
        float4 wa = *reinterpret_cast<const float4*>(&w1s[k * 32 + cg * 8]);
        float4 wb = *reinterpret_cast<const float4*>(&w1s[k * 32 + cg * 8 + 4]);
        float w[8] = {wa.x, wa.y, wa.z, wa.w, wb.x, wb.y, wb.z, wb.w};
        float xv[4] = {x0[k], x1[k], x2[k], x3[k]};
        #pragma unroll
        for (int j = 0; j < 4; j++)
            #pragma unroll
            for (int m = 0; m < 8; m++)
                acc[j][m] = fmaf(xv[j], w[m], acc[j][m]);
    }

    // relu + round-trip h through smem (reuse xs region)
    __syncthreads();
    float* ht = xs;   // [FNB][XSTR]
    #pragma unroll
    for (int j = 0; j < 4; j++) {
        int n = 4 * q + j;
        #pragma unroll
        for (int m = 0; m < 8; m++)
            ht[n * XSTR + cg * 8 + m] = fmaxf(acc[j][m], 0.f);
    }
    __syncthreads();

    // layer 2
    float o[4][8];
    #pragma unroll
    for (int j = 0; j < 4; j++)
        #pragma unroll
        for (int m = 0; m < 8; m++) o[j][m] = b2s[cg * 8 + m];

    const float* h0 = &ht[(4 * q + 0) * XSTR];
    const float* h1 = &ht[(4 * q + 1) * XSTR];
    const float* h2 = &ht[(4 * q + 2) * XSTR];
    const float* h3 = &ht[(4 * q + 3) * XSTR];

    #pragma unroll 4
    for (int i = 0; i < 32; i++) {
        float4 wa = *reinterpret_cast<const float4*>(&w2s[i * 32 + cg * 8]);
        float4 wb = *reinterpret_cast<const float4*>(&w2s[i * 32 + cg * 8 + 4]);
        float w[8] = {wa.x, wa.y, wa.z, wa.w, wb.x, wb.y, wb.z, wb.w};
        float hv[4] = {h0[i], h1[i], h2[i], h3[i]};
        #pragma unroll
        for (int j = 0; j < 4; j++)
            #pragma unroll
            for (int m = 0; m < 8; m++)
                o[j][m] = fmaf(hv[j], w[m], o[j][m]);
    }

    #pragma unroll
    for (int j = 0; j < 4; j++) {
        int n = 4 * q + j;
        if (n < nvalid) {
            float* dst = out + (size_t)(base + n) * OUT_FEAT + cg * 8;
            reinterpret_cast<float4*>(dst)[0] =
                make_float4(o[j][0], o[j][1], o[j][2], o[j][3]);
            reinterpret_cast<float4*>(dst)[1] =
                make_float4(o[j][4], o[j][5], o[j][6], o[j][7]);
        }
    }
}

// ---------------------------------------------------------------------------
// Launch: zero ->(PDL) fused ->(PDL) final.
// ---------------------------------------------------------------------------
static void launch_pdl(const void* func, dim3 grid, dim3 block, size_t smem,
                       void** args) {
    cudaLaunchConfig_t cfg = {};
    cfg.gridDim = grid;
    cfg.blockDim = block;
    cfg.dynamicSmemBytes = smem;
    cudaLaunchAttribute attr[1];
    attr[0].id = cudaLaunchAttributeProgrammaticStreamSerialization;
    attr[0].val.programmaticStreamSerializationAllowed = 1;
    cfg.attrs = attr;
    cfg.numAttrs = 1;
    cudaLaunchKernelExC(&cfg, func, args);
}

extern "C" void kernel_launch(void* const* d_in, const int* in_sizes, int n_in,
                              void* d_out, int out_size) {
    const float* node_attr   = (const float*)d_in[0];
    const int*   edge_index  = (const int*)d_in[1];
    const float* edge_attr   = (const float*)d_in[2];
    const float* global_attr = (const float*)d_in[3];
    const float* W1          = (const float*)d_in[4];
    const float* b1          = (const float*)d_in[5];
    const float* W2          = (const float*)d_in[6];
    const float* b2          = (const float*)d_in[7];
    float*       out         = (float*)d_out;

    const int* receivers = edge_index + N_EDGES;

    zero_kernel<<<Z_BLOCKS, TPB>>>();

    {
        void* args[] = { (void*)&edge_attr, (void*)&receivers,
                         (void*)&node_attr, (void*)&global_attr,
                         (void*)&W1, (void*)&b1 };
        launch_pdl((const void*)fused_scatter_partial,
                   dim3(T_BLOCKS), dim3(TPB),
                   SMEM1_FLOATS * sizeof(float), args);
    }

    {
        void* args[] = { (void*)&W1, (void*)&W2, (void*)&b2, (void*)&out };
        launch_pdl((const void*)final_kernel,
                   dim3(F_BLOCKS), dim3(FTPB),
                   SMEM2_FLOATS * sizeof(float), args);
    }
    (void)in_sizes; (void)n_in; (void)out_size;
}

// round 17
// speedup vs baseline: 1.0829x; 1.0004x over previous
#include <cuda_runtime.h>
#include <cstdint>

#define N_NODES   100000
#define N_EDGES   1600000
#define D         32
#define OUT_FEAT  32

__device__ __align__(16) float g_agg[N_NODES * D];       // segment_sum result
__device__ __align__(16) float g_partial[N_NODES * D];   // node@W1[0:32] + gb

#define TPB  128
#define NB   128
#define XSTR 33

#define P_BLOCKS     782                      // ceil(100000 / 128)
#define EPB          128                      // edges per scatter block
#define S_BLOCKS     (N_EDGES / EPB)          // 12500 exactly
#define T_BLOCKS     (S_BLOCKS + P_BLOCKS)    // 13282

#define SMEM1_FLOATS (NB * XSTR + 32 * 32 + 32)

// final kernel: TPB=64, NB=64 (same 4x8 per-thread tile, 2x the blocks)
#define FTPB 64
#define FNB  64
#define F_BLOCKS ((N_NODES + FNB - 1) / FNB)  // 1563
#define SMEM2_FLOATS (FNB * XSTR + 32 * 32 + 32 * 32 + 32)

#define PDL_TRIGGER() asm volatile("griddepcontrol.launch_dependents;" ::: "memory")
#define PDL_WAIT()    asm volatile("griddepcontrol.wait;" ::: "memory")

// ---------------------------------------------------------------------------
// Kernel 0: zero g_agg. Reshaped: 200 blocks x 256 threads x 16 STG.128
// (exactly 819200 f4 = 12.8MB, ~1.35 waves) — issue/store-bound instead of
// the old 1600-tiny-block scheduling-bound shape (5.9us -> ~1.5us).
// ---------------------------------------------------------------------------
#define Z_BLOCKS 200
#define Z_TPB    256
__global__ __launch_bounds__(Z_TPB) void zero_kernel() {
    PDL_TRIGGER();
    float4* p = reinterpret_cast<float4*>(g_agg);
    const int i0 = blockIdx.x * (Z_TPB * 16) + threadIdx.x;
    const float4 z = make_float4(0.f, 0.f, 0.f, 0.f);
    #pragma unroll
    for (int t = 0; t < 16; t++) p[i0 + Z_TPB * t] = z;
}

// ---------------------------------------------------------------------------
// Kernel 1 (fused): scatter blocks stage 128 edges in smem and issue ONE
// cp.reduce.async.bulk (128B) per edge — TMA/L2-side RMW. Partial-MLP
// blocks Bresenham-interleaved. (Proven configuration, unchanged.)
// ---------------------------------------------------------------------------
__global__ __launch_bounds__(TPB) void fused_scatter_partial(
    const float* __restrict__ edge_attr,
    const int* __restrict__ receivers,
    const float* __restrict__ node_attr,
    const float* __restrict__ global_attr,
    const float* __restrict__ W1,
    const float* __restrict__ b1)
{
    PDL_TRIGGER();
    const int tid = threadIdx.x;

    const long long a = (long long)blockIdx.x * P_BLOCKS;
    const int p_before = (int)(a / T_BLOCKS);
    const int p_after  = (int)((a + P_BLOCKS) / T_BLOCKS);
    const bool is_partial = (p_after > p_before);

    extern __shared__ float smem[];

    if (!is_partial) {
        float4* b4 = reinterpret_cast<float4*>(smem);   // 1024 f4 = 128 edges
        const int s_idx = blockIdx.x - p_before;
        const int e0 = s_idx * EPB;

        const float4* src = reinterpret_cast<const float4*>(edge_attr) + (size_t)e0 * 8;
        float4 v[8];
        #pragma unroll
        for (int t = 0; t < 8; t++) v[t] = src[tid + 128 * t];
        const int r = receivers[e0 + tid];

        #pragma unroll
        for (int t = 0; t < 8; t++) b4[tid + 128 * t] = v[t];

        asm volatile("fence.proxy.async.shared::cta;" ::: "memory");
        __syncthreads();

        PDL_WAIT();   // g_agg fully zeroed beyond this point

        uint32_t sb;
        asm("{ .reg .u64 t; cvta.to.shared.u64 t, %1; cvt.u32.u64 %0, t; }"
            : "=r"(sb) : "l"(smem));

        if ((unsigned)r < N_NODES) {
            float* dst = g_agg + (size_t)r * D;
            asm volatile(
                "cp.reduce.async.bulk.global.shared::cta.bulk_group.add.f32 "
                "[%0], [%1], 128;"
                :: "l"(dst), "r"(sb + (unsigned)tid * 128)
                : "memory");
        }
        asm volatile("cp.async.bulk.commit_group;" ::: "memory");
        asm volatile("cp.async.bulk.wait_group 0;" ::: "memory");
        return;
    }

    // -------- partial-MLP path (unchanged, proven) ---------------------------
    float* xs  = smem;                 // [NB][XSTR]
    float* w1s = xs + NB * XSTR;       // [32][32]  W1 rows 0..31
    float* gb  = w1s + 32 * 32;        // [32]

    const int cg   = tid & 3;
    const int q    = tid >> 2;
    const int base = p_before * NB;
    const int nvalid = min(NB, N_NODES - base);
    const bool full  = (nvalid == NB);

    {
        const float4* w1v = reinterpret_cast<const float4*>(W1);
        float4 a0 = w1v[tid], a1 = w1v[tid + 128];
        reinterpret_cast<float4*>(w1s)[tid]       = a0;
        reinterpret_cast<float4*>(w1s)[tid + 128] = a1;
    }
    if (tid < 32) {
        float acc = b1[tid];
        #pragma unroll
        for (int k = 0; k < D; k++)
            acc = fmaf(global_attr[k], W1[(64 + k) * 32 + tid], acc);
        gb[tid] = acc;
    }
    {
        const float4* nav = reinterpret_cast<const float4*>(node_attr) + (size_t)base * 8;
        float4 va[8];
        #pragma unroll
        for (int t = 0; t < 8; t++) {
            int idx = tid + 128 * t;
            if (full || (idx >> 3) < nvalid) va[t] = nav[idx];
            else va[t] = make_float4(0, 0, 0, 0);
        }
        #pragma unroll
        for (int t = 0; t < 8; t++) {
            int idx = tid + 128 * t;
            int n = idx >> 3, c = idx & 7;
            float* p = &xs[n * XSTR + 4 * c];
            p[0] = va[t].x; p[1] = va[t].y; p[2] = va[t].z; p[3] = va[t].w;
        }
    }
    __syncthreads();

    float acc[4][8];
    #pragma unroll
    for (int j = 0; j < 4; j++)
        #pragma unroll
        for (int m = 0; m < 8; m++) acc[j][m] = gb[cg * 8 + m];

    const float* x0 = &xs[(4 * q + 0) * XSTR];
    const float* x1 = &xs[(4 * q + 1) * XSTR];
    const float* x2 = &xs[(4 * q + 2) * XSTR];
    const float* x3 = &xs[(4 * q + 3) * XSTR];

    #pragma unroll 4
    for (int k = 0; k < 32; k++) {
        float4 wa = *reinterpret_cast<const float4*>(&w1s[k * 32 + cg * 8]);
        float4 wb = *reinterpret_cast<const float4*>(&w1s[k * 32 + cg * 8 + 4]);
        float w[8] = {wa.x, wa.y, wa.z, wa.w, wb.x, wb.y, wb.z, wb.w};
        float xv[4] = {x0[k], x1[k], x2[k], x3[k]};
        #pragma unroll
        for (int j = 0; j < 4; j++)
            #pragma unroll
            for (int m = 0; m < 8; m++)
                acc[j][m] = fmaf(xv[j], w[m], acc[j][m]);
    }

    #pragma unroll
    for (int j = 0; j < 4; j++) {
        int n = 4 * q + j;
        if (n < nvalid) {
            float* dst = g_partial + (size_t)(base + n) * D + cg * 8;
            reinterpret_cast<float4*>(dst)[0] =
                make_float4(acc[j][0], acc[j][1], acc[j][2], acc[j][3]);
            reinterpret_cast<float4*>(dst)[1] =
                make_float4(acc[j][4], acc[j][5], acc[j][6], acc[j][7]);
        }
    }
}

// ---------------------------------------------------------------------------
// Kernel 2 (PDL secondary): TPB=64, NB=64 — 4x8 per-thread tile, 1563 blocks.
// ---------------------------------------------------------------------------
__global__ __launch_bounds__(FTPB) void final_kernel(
    const float* __restrict__ W1,
    const float* __restrict__ W2, const float* __restrict__ b2,
    float* __restrict__ out)
{
    extern __shared__ float smem[];
    float* xs  = smem;                 // [FNB][XSTR] agg; reused as ht
    float* w1s = xs + FNB * XSTR;      // [32][32]  W1 rows 32..63
    float* w2s = w1s + 32 * 32;        // [32][32]
    float* b2s = w2s + 32 * 32;        // [32]

    const int tid  = threadIdx.x;      // 0..63
    const int cg   = tid & 3;
    const int q    = tid >> 2;         // 0..15
    const int base = blockIdx.x * FNB;
    const int nvalid = min(FNB, N_NODES - base);
    const bool full  = (nvalid == FNB);

    // -------- PRE-WAIT: weights/biases are pure inputs ----------------------
    {
        const float4* w1v = reinterpret_cast<const float4*>(W1);
        const float4* w2v = reinterpret_cast<const float4*>(W2);
        float4 a0 = w1v[256 + tid],       a1 = w1v[256 + tid + 64];
        float4 a2 = w1v[256 + tid + 128], a3 = w1v[256 + tid + 192];
        float4 c0 = w2v[tid],             c1 = w2v[tid + 64];
        float4 c2 = w2v[tid + 128],       c3 = w2v[tid + 192];
        reinterpret_cast<float4*>(w1s)[tid]       = a0;
        reinterpret_cast<float4*>(w1s)[tid + 64]  = a1;
        reinterpret_cast<float4*>(w1s)[tid + 128] = a2;
        reinterpret_cast<float4*>(w1s)[tid + 192] = a3;
        reinterpret_cast<float4*>(w2s)[tid]       = c0;
        reinterpret_cast<float4*>(w2s)[tid + 64]  = c1;
        reinterpret_cast<float4*>(w2s)[tid + 128] = c2;
        reinterpret_cast<float4*>(w2s)[tid + 192] = c3;
    }
    if (tid < 32) b2s[tid] = b2[tid];

    PDL_WAIT();   // g_agg and g_partial complete beyond this point

    {
        const float4* agv = reinterpret_cast<const float4*>(g_agg) + (size_t)base * 8;
        float4 vb[8];
        #pragma unroll
        for (int t = 0; t < 8; t++) {
            int idx = tid + 64 * t;
            if (full || (idx >> 3) < nvalid) vb[t] = agv[idx];
            else vb[t] = make_float4(0, 0, 0, 0);
        }
        #pragma unroll
        for (int t = 0; t < 8; t++) {
            int idx = tid + 64 * t;
            int n = idx >> 3, c = idx & 7;
            float* p = &xs[n * XSTR + 4 * c];
            p[0] = vb[t].x; p[1] = vb[t].y; p[2] = vb[t].z; p[3] = vb[t].w;
        }
    }

    float acc[4][8];
    {
        const float4* pv = reinterpret_cast<const float4*>(g_partial) + (size_t)base * 8;
        #pragma unroll
        for (int j = 0; j < 4; j++) {
            int n = 4 * q + j;
            float4 pa, pb;
            if (full || n < nvalid) {
                pa = pv[n * 8 + cg * 2];
                pb = pv[n * 8 + cg * 2 + 1];
            } else { pa = make_float4(0,0,0,0); pb = pa; }
            acc[j][0] = pa.x; acc[j][1] = pa.y; acc[j][2] = pa.z; acc[j][3] = pa.w;
            acc[j][4] = pb.x; acc[j][5] = pb.y; acc[j][6] = pb.z; acc[j][7] = pb.w;
        }
    }
    __syncthreads();

    const float* x0 = &xs[(4 * q + 0) * XSTR];
    const float* x1 = &xs[(4 * q + 1) * XSTR];
    const float* x2 = &xs[(4 * q + 2) * XSTR];
    const float* x3 = &xs[(4 * q + 3) * XSTR];

    #pragma unroll 4
    for (int k = 0; k < 32; k++) {
        float4 wa = *reinterpret_cast<const float4*>(&w1s[k * 32 + cg * 8]);
        float4 wb = *reinterpret_cast<const float4*>(&w1s[k * 32 + cg * 8 + 4]);
        float w[8] = {wa.x, wa.y, wa.z, wa.w, wb.x, wb.y, wb.z, wb.w};
        float xv[4] = {x0[k], x1[k], x2[k], x3[k]};
        #pragma unroll
        for (int j = 0; j < 4; j++)
            #pragma unroll
            for (int m = 0; m < 8; m++)
                acc[j][m] = fmaf(xv[j], w[m], acc[j][m]);
    }

    __syncthreads();
    float* ht = xs;   // [FNB][XSTR]
    #pragma unroll
    for (int j = 0; j < 4; j++) {
        int n = 4 * q + j;
        #pragma unroll
        for (int m = 0; m < 8; m++)
            ht[n * XSTR + cg * 8 + m] = fmaxf(acc[j][m], 0.f);
    }
    __syncthreads();

    float o[4][8];
    #pragma unroll
    for (int j = 0; j < 4; j++)
        #pragma unroll
        for (int m = 0; m < 8; m++) o[j][m] = b2s[cg * 8 + m];

    const float* h0 = &ht[(4 * q + 0) * XSTR];
    const float* h1 = &ht[(4 * q + 1) * XSTR];
    const float* h2 = &ht[(4 * q + 2) * XSTR];
    const float* h3 = &ht[(4 * q + 3) * XSTR];

    #pragma unroll 4
    for (int i = 0; i < 32; i++) {
        float4 wa = *reinterpret_cast<const float4*>(&w2s[i * 32 + cg * 8]);
        float4 wb = *reinterpret_cast<const float4*>(&w2s[i * 32 + cg * 8 + 4]);
        float w[8] = {wa.x, wa.y, wa.z, wa.w, wb.x, wb.y, wb.z, wb.w};
        float hv[4] = {h0[i], h1[i], h2[i], h3[i]};
        #pragma unroll
        for (int j = 0; j < 4; j++)
            #pragma unroll
            for (int m = 0; m < 8; m++)
                o[j][m] = fmaf(hv[j], w[m], o[j][m]);
    }

    #pragma unroll
    for (int j = 0; j < 4; j++) {
        int n = 4 * q + j;
        if (n < nvalid) {
            float* dst = out + (size_t)(base + n) * OUT_FEAT + cg * 8;
            reinterpret_cast<float4*>(dst)[0] =
                make_float4(o[j][0], o[j][1], o[j][2], o[j][3]);
            reinterpret_cast<float4*>(dst)[1] =
                make_float4(o[j][4], o[j][5], o[j][6], o[j][7]);
        }
    }
}

// ---------------------------------------------------------------------------
// Launch: zero ->(PDL) fused ->(PDL) final.
// ---------------------------------------------------------------------------
static void launch_pdl(const void* func, dim3 grid, dim3 block, size_t smem,
                       void** args) {
    cudaLaunchConfig_t cfg = {};
    cfg.gridDim = grid;
    cfg.blockDim = block;
    cfg.dynamicSmemBytes = smem;
    cudaLaunchAttribute attr[1];
    attr[0].id = cudaLaunchAttributeProgrammaticStreamSerialization;
    attr[0].val.programmaticStreamSerializationAllowed = 1;
    cfg.attrs = attr;
    cfg.numAttrs = 1;
    cudaLaunchKernelExC(&cfg, func, args);
}

extern "C" void kernel_launch(void* const* d_in, const int* in_sizes, int n_in,
                              void* d_out, int out_size) {
    const float* node_attr   = (const float*)d_in[0];
    const int*   edge_index  = (const int*)d_in[1];
    const float* edge_attr   = (const float*)d_in[2];
    const float* global_attr = (const float*)d_in[3];
    const float* W1          = (const float*)d_in[4];
    const float* b1          = (const float*)d_in[5];
    const float* W2          = (const float*)d_in[6];
    const float* b2          = (const float*)d_in[7];
    float*       out         = (float*)d_out;

    const int* receivers = edge_index + N_EDGES;

    zero_kernel<<<Z_BLOCKS, Z_TPB>>>();

    {
        void* args[] = { (void*)&edge_attr, (void*)&receivers,
                         (void*)&node_attr, (void*)&global_attr,
                         (void*)&W1, (void*)&b1 };
        launch_pdl((const void*)fused_scatter_partial,
                   dim3(T_BLOCKS), dim3(TPB),
                   SMEM1_FLOATS * sizeof(float), args);
    }

    {
        void* args[] = { (void*)&W1, (void*)&W2, (void*)&b2, (void*)&out };
        launch_pdl((const void*)final_kernel,
                   dim3(F_BLOCKS), dim3(FTPB),
                   SMEM2_FLOATS * sizeof(float), args);
    }
    (void)in_sizes; (void)n_in; (void)out_size;
}